// round 5
// baseline (speedup 1.0000x reference)
#include <cuda_runtime.h>
#include <cstdint>

#define N_TOK 4096
#define NH 12
#define HD 64
#define DMODEL 768
#define QK_SCALE 0.125f
#define LOG2E 1.4426950408889634f
#define NSPLIT 2
#define KEYS_PER_SPLIT (N_TOK / NSPLIT)

// Scratch (device globals: allocation-free per harness rules)
__device__ float g_qkv[(size_t)N_TOK * 3 * DMODEL];   // raw qkv (fp32)
__device__ float g_q[(size_t)NH * N_TOK * HD];        // [h][n][d'] d-permuted, *scale*log2e, tf32
__device__ float g_k[(size_t)NH * N_TOK * HD];        // [h][n][d'] d-permuted, tf32
__device__ float g_vt[(size_t)NH * HD * N_TOK];       // [h][d][n'] key-permuted V^T, tf32
__device__ float g_att[(size_t)N_TOK * DMODEL];       // attention out [n][h*HD+d], tf32-rounded
__device__ float g_hs[(size_t)N_TOK * DMODEL];        // tf32-rounded hidden_states
__device__ float g_w1[(size_t)DMODEL * 3 * DMODEL];   // tf32-rounded qkv_w
__device__ float g_w2[(size_t)DMODEL * DMODEL];       // tf32-rounded proj_w
// split-K partials
__device__ float g_po[(size_t)NSPLIT * NH * N_TOK * HD];  // unnormalized O
__device__ float g_pm[(size_t)NSPLIT * NH * N_TOK];       // log2-domain running max
__device__ float g_pl[(size_t)NSPLIT * NH * N_TOK];       // running sum

// ---------------------------------------------------------------------------
// helpers
// ---------------------------------------------------------------------------
__device__ __forceinline__ uint32_t f2tf(float f) {
    uint32_t u;
    asm("cvt.rna.tf32.f32 %0, %1;" : "=r"(u) : "f"(f));
    return u;
}
__device__ __forceinline__ float ex2(float x) {
    float y;
    asm("ex2.approx.f32 %0, %1;" : "=f"(y) : "f"(x));
    return y;
}
__device__ __forceinline__ void mma_tf32(float& c0, float& c1, float& c2, float& c3,
                                         uint32_t a0, uint32_t a1, uint32_t a2, uint32_t a3,
                                         uint32_t b0, uint32_t b1) {
    asm volatile(
        "mma.sync.aligned.m16n8k8.row.col.f32.tf32.tf32.f32 "
        "{%0,%1,%2,%3}, {%4,%5,%6,%7}, {%8,%9}, {%0,%1,%2,%3};\n"
        : "+f"(c0), "+f"(c1), "+f"(c2), "+f"(c3)
        : "r"(a0), "r"(a1), "r"(a2), "r"(a3), "r"(b0), "r"(b1));
}
__device__ __forceinline__ void cp16(uint32_t dst, const void* src) {
    asm volatile("cp.async.cg.shared.global [%0], [%1], 16;" :: "r"(dst), "l"(src));
}
#define CP_COMMIT() asm volatile("cp.async.commit_group;")
#define CP_WAIT(n)  asm volatile("cp.async.wait_group %0;" :: "n"(n))

// pair-interleave permutation within each 8-group: j<4 -> 2j ; j>=4 -> 2(j-4)+1
__device__ __forceinline__ int pperm(int j) {
    int r = j & 7;
    return (j & ~7) | ((r < 4) ? (2 * r) : (2 * (r - 4) + 1));
}

// ---------------------------------------------------------------------------
// pre-round hs / qkv_w / proj_w to tf32 (lets GEMMs use raw cp.async)
// ---------------------------------------------------------------------------
#define N_HS4 (N_TOK * DMODEL / 4)
#define N_W14 (DMODEL * 3 * DMODEL / 4)
#define N_W24 (DMODEL * DMODEL / 4)

__global__ void __launch_bounds__(256) preround(const float4* __restrict__ hs,
                                                const float4* __restrict__ w1,
                                                const float4* __restrict__ w2)
{
    int i = blockIdx.x * 256 + threadIdx.x;
    float4 v; float4* dst;
    if (i < N_HS4)              { v = hs[i];               dst = (float4*)g_hs + i; }
    else if (i < N_HS4 + N_W14) { v = w1[i - N_HS4];       dst = (float4*)g_w1 + (i - N_HS4); }
    else if (i < N_HS4 + N_W14 + N_W24) {
        v = w2[i - N_HS4 - N_W14]; dst = (float4*)g_w2 + (i - N_HS4 - N_W14);
    } else return;
    float4 o = make_float4(__uint_as_float(f2tf(v.x)), __uint_as_float(f2tf(v.y)),
                           __uint_as_float(f2tf(v.z)), __uint_as_float(f2tf(v.w)));
    *dst = o;
}

// ---------------------------------------------------------------------------
// tf32 GEMM with cp.async double-buffered k-chunks.
// C[M,Nc] = A[M,K] @ B[K,Nc] + bias.  128x128x32 tiles, 256 thr, 2 CTA/SM.
// ---------------------------------------------------------------------------
#define AS_S 36
#define BS_S 136
#define A_BUF (128 * AS_S)
#define B_BUF (32 * BS_S)
#define GEMM_SMEM ((2 * A_BUF + 2 * B_BUF) * 4)

__global__ void __launch_bounds__(256, 2) gemm_tf32(
    const float* __restrict__ A, const float* __restrict__ B,
    const float* __restrict__ bias, float* __restrict__ C,
    int M, int Nc, int K)
{
    extern __shared__ uint32_t smg[];
    uint32_t* As = smg;
    uint32_t* Bs = smg + 2 * A_BUF;

    const int tid = threadIdx.x;
    const int lane = tid & 31;
    const int w = tid >> 5;
    const int wm = w >> 2, wn = w & 3;
    const int bx = blockIdx.x, by = blockIdx.y;

    const float* Ag = A + (size_t)(by * 128) * K;
    const float* Bg = B + bx * 128;

    const uint32_t as_u = (uint32_t)__cvta_generic_to_shared(As);
    const uint32_t bs_u = (uint32_t)__cvta_generic_to_shared(Bs);

    float acc[4][4][4];
#pragma unroll
    for (int mt = 0; mt < 4; mt++)
#pragma unroll
        for (int nt = 0; nt < 4; nt++)
#pragma unroll
            for (int c = 0; c < 4; c++) acc[mt][nt][c] = 0.f;

    const int NC = K / 32;

#pragma unroll
    for (int i = 0; i < 4; i++) {
        int id = tid + i * 256;
        int r = id >> 3, c = (id & 7) * 4;
        cp16(as_u + (uint32_t)(r * AS_S + c) * 4, Ag + (size_t)r * K + c);
    }
#pragma unroll
    for (int i = 0; i < 4; i++) {
        int id = tid + i * 256;
        int r = id >> 5, c = (id & 31) * 4;
        cp16(bs_u + (uint32_t)(r * BS_S + c) * 4, Bg + (size_t)r * Nc + c);
    }
    CP_COMMIT();

    for (int ch = 0; ch < NC; ch++) {
        if (ch + 1 < NC) {
            int k0 = (ch + 1) * 32;
            int buf = (ch + 1) & 1;
#pragma unroll
            for (int i = 0; i < 4; i++) {
                int id = tid + i * 256;
                int r = id >> 3, c = (id & 7) * 4;
                cp16(as_u + (uint32_t)(buf * A_BUF + r * AS_S + c) * 4,
                     Ag + (size_t)r * K + k0 + c);
            }
#pragma unroll
            for (int i = 0; i < 4; i++) {
                int id = tid + i * 256;
                int r = id >> 5, c = (id & 31) * 4;
                cp16(bs_u + (uint32_t)(buf * B_BUF + r * BS_S + c) * 4,
                     Bg + (size_t)(k0 + r) * Nc + c);
            }
        }
        CP_COMMIT();
        CP_WAIT(1);
        __syncthreads();

        const uint32_t* Ab = As + (ch & 1) * A_BUF;
        const uint32_t* Bb = Bs + (ch & 1) * B_BUF;

#pragma unroll
        for (int ks = 0; ks < 4; ks++) {
            const int kk = ks * 8 + (lane & 3);
            uint32_t a[4][4], b[4][2];
#pragma unroll
            for (int mt = 0; mt < 4; mt++) {
                int r = wm * 64 + mt * 16 + (lane >> 2);
                a[mt][0] = Ab[r * AS_S + kk];
                a[mt][1] = Ab[(r + 8) * AS_S + kk];
                a[mt][2] = Ab[r * AS_S + kk + 4];
                a[mt][3] = Ab[(r + 8) * AS_S + kk + 4];
            }
#pragma unroll
            for (int nt = 0; nt < 4; nt++) {
                int cn = wn * 32 + nt * 8 + (lane >> 2);
                b[nt][0] = Bb[kk * BS_S + cn];
                b[nt][1] = Bb[(kk + 4) * BS_S + cn];
            }
#pragma unroll
            for (int mt = 0; mt < 4; mt++)
#pragma unroll
                for (int nt = 0; nt < 4; nt++)
                    mma_tf32(acc[mt][nt][0], acc[mt][nt][1], acc[mt][nt][2], acc[mt][nt][3],
                             a[mt][0], a[mt][1], a[mt][2], a[mt][3],
                             b[nt][0], b[nt][1]);
        }
        __syncthreads();
    }

#pragma unroll
    for (int mt = 0; mt < 4; mt++) {
#pragma unroll
        for (int nt = 0; nt < 4; nt++) {
            int r = by * 128 + wm * 64 + mt * 16 + (lane >> 2);
            int cn = bx * 128 + wn * 32 + nt * 8 + 2 * (lane & 3);
            float b0 = bias[cn], b1 = bias[cn + 1];
            float2 v0 = make_float2(acc[mt][nt][0] + b0, acc[mt][nt][1] + b1);
            float2 v1 = make_float2(acc[mt][nt][2] + b0, acc[mt][nt][3] + b1);
            *(float2*)(C + (size_t)r * Nc + cn) = v0;
            *(float2*)(C + (size_t)(r + 8) * Nc + cn) = v1;
        }
    }
}

// ---------------------------------------------------------------------------
// RoPE + scale + split q/k into [h][n][d'] with pair-interleaved d (tf32)
// ---------------------------------------------------------------------------
__global__ void __launch_bounds__(256) rope_split(const float* __restrict__ cosp,
                                                  const float* __restrict__ sinp)
{
    int idx = blockIdx.x * 256 + threadIdx.x;
    if (idx >= N_TOK * NH * HD) return;
    int d = idx & 63;
    int h = (idx >> 6) % NH;
    int n = idx / (NH * HD);

    float c = cosp[n * HD + d];
    float s = sinp[n * HD + d];
    const float* base = g_qkv + (size_t)n * (3 * DMODEL) + h * HD;
    float qv = base[d];
    float kv = base[DMODEL + d];
    int dp = (d < 32) ? d + 32 : d - 32;
    float sgn = (d < 32) ? -1.f : 1.f;
    float qr = sgn * base[dp];
    float kr = sgn * base[DMODEL + dp];

    size_t o = ((size_t)h * N_TOK + n) * HD + pperm(d);
    g_q[o] = __uint_as_float(f2tf((qv * c + qr * s) * (QK_SCALE * LOG2E)));
    g_k[o] = __uint_as_float(f2tf(kv * c + kr * s));
}

// ---------------------------------------------------------------------------
// V transpose: g_qkv v-part [n][h*64+d] -> g_vt [h][d][perm(n)] (tf32)
// ---------------------------------------------------------------------------
__global__ void __launch_bounds__(256) v_transpose()
{
    __shared__ float sm[64 * 65];
    const int h = blockIdx.y;
    const int nb = blockIdx.x;
    const int tid = threadIdx.x;

#pragma unroll
    for (int i = 0; i < 16; i++) {
        int idx = tid + i * 256;
        int nl = idx >> 6, d = idx & 63;
        sm[nl * 65 + d] = g_qkv[(size_t)(nb * 64 + nl) * (3 * DMODEL) + 2 * DMODEL + h * HD + d];
    }
    __syncthreads();
#pragma unroll
    for (int i = 0; i < 16; i++) {
        int idx = tid + i * 256;
        int d = idx >> 6, nl = idx & 63;
        float v = sm[nl * 65 + d];
        g_vt[((size_t)(h * HD + d)) * N_TOK + nb * 64 + pperm(nl)] =
            __uint_as_float(f2tf(v));
    }
}

// ---------------------------------------------------------------------------
// Flash attention, split-K (NSPLIT key ranges), tf32 mma, LDS.64 fragments,
// cp.async double-buffered 64-key tiles. Writes unnormalized partials.
// ---------------------------------------------------------------------------
#define KT 64
#define NTILES (KEYS_PER_SPLIT / KT)   // 32
#define ST 72
#define ATTN_SMEM ((128 * ST + 2 * KT * ST + 2 * KT * ST) * 4)

__global__ void __launch_bounds__(256, 2) attn_mma()
{
    extern __shared__ uint32_t sm[];
    uint32_t* Qs = sm;                   // [128][ST]
    uint32_t* Ks = Qs + 128 * ST;        // [2][KT][ST]
    uint32_t* Vs = Ks + 2 * KT * ST;     // [2][HD][ST]

    const int h = blockIdx.y;
    const int qb = blockIdx.x;
    const int sp = blockIdx.z;
    const int tid = threadIdx.x;
    const int lane = tid & 31;
    const int w = tid >> 5;

    const float* qg = g_q + ((size_t)h * N_TOK + (size_t)qb * 128) * HD;
    const float* kg = g_k + ((size_t)h * N_TOK + (size_t)sp * KEYS_PER_SPLIT) * HD;
    const float* vtg = g_vt + (size_t)h * HD * N_TOK + (size_t)sp * KEYS_PER_SPLIT;

    const uint32_t ks_u32 = (uint32_t)__cvta_generic_to_shared(Ks);
    const uint32_t vs_u32 = (uint32_t)__cvta_generic_to_shared(Vs);

#pragma unroll
    for (int i = 0; i < 8; i++) {
        int id = tid + i * 256;
        int r = id >> 4, c = (id & 15) * 4;
        *(uint4*)&Qs[r * ST + c] = *(const uint4*)(qg + r * HD + c);
    }

#pragma unroll
    for (int t = 0; t < 2; t++) {
        const float* kt = kg + (size_t)t * KT * HD;
#pragma unroll
        for (int i = 0; i < 4; i++) {
            int id = tid + i * 256;
            int r = id >> 4, c = (id & 15) * 4;
            cp16(ks_u32 + (uint32_t)(t * KT * ST + r * ST + c) * 4, kt + r * HD + c);
            cp16(vs_u32 + (uint32_t)(t * KT * ST + r * ST + c) * 4,
                 vtg + (size_t)r * N_TOK + t * KT + c);
        }
        CP_COMMIT();
    }

    float o[8][4];
#pragma unroll
    for (int nt = 0; nt < 8; nt++)
#pragma unroll
        for (int c = 0; c < 4; c++) o[nt][c] = 0.f;
    float m0 = -1e30f, m1 = -1e30f, l0 = 0.f, l1 = 0.f;

    const int qrow = w * 16 + (lane >> 2);
    const int q4 = lane & 3;
    const int srcA = (lane & ~3) | (q4 >> 1);
    const int srcB = srcA + 2;
    const bool odd = q4 & 1;

    for (int t = 0; t < NTILES; t++) {
        CP_WAIT(1);
        __syncthreads();
        const uint32_t* Kb = Ks + (t & 1) * KT * ST;
        const uint32_t* Vb = Vs + (t & 1) * KT * ST;

        // ---- S = Q K^T
        float s[8][4];
#pragma unroll
        for (int nt = 0; nt < 8; nt++)
#pragma unroll
            for (int c = 0; c < 4; c++) s[nt][c] = 0.f;

#pragma unroll
        for (int ks = 0; ks < 8; ks++) {
            const int kc = ks * 8 + 2 * q4;
            uint2 aA = *(const uint2*)&Qs[qrow * ST + kc];
            uint2 aB = *(const uint2*)&Qs[(qrow + 8) * ST + kc];
#pragma unroll
            for (int nt = 0; nt < 8; nt++) {
                int nn = nt * 8 + (lane >> 2);
                uint2 b = *(const uint2*)&Kb[nn * ST + kc];
                mma_tf32(s[nt][0], s[nt][1], s[nt][2], s[nt][3],
                         aA.x, aB.x, aA.y, aB.y, b.x, b.y);
            }
        }

        // ---- online softmax (log2 domain)
        {
            float mt = -1e30f;
#pragma unroll
            for (int nt = 0; nt < 8; nt++)
                mt = fmaxf(mt, fmaxf(s[nt][0], s[nt][1]));
            mt = fmaxf(mt, __shfl_xor_sync(0xffffffffu, mt, 1));
            mt = fmaxf(mt, __shfl_xor_sync(0xffffffffu, mt, 2));
            float nm = fmaxf(m0, mt);
            float al = ex2(m0 - nm);
            m0 = nm;
            float rs = 0.f;
#pragma unroll
            for (int nt = 0; nt < 8; nt++) {
                s[nt][0] = ex2(s[nt][0] - nm);
                s[nt][1] = ex2(s[nt][1] - nm);
                rs += s[nt][0] + s[nt][1];
            }
            rs += __shfl_xor_sync(0xffffffffu, rs, 1);
            rs += __shfl_xor_sync(0xffffffffu, rs, 2);
            l0 = l0 * al + rs;
#pragma unroll
            for (int nt = 0; nt < 8; nt++) { o[nt][0] *= al; o[nt][1] *= al; }
        }
        {
            float mt = -1e30f;
#pragma unroll
            for (int nt = 0; nt < 8; nt++)
                mt = fmaxf(mt, fmaxf(s[nt][2], s[nt][3]));
            mt = fmaxf(mt, __shfl_xor_sync(0xffffffffu, mt, 1));
            mt = fmaxf(mt, __shfl_xor_sync(0xffffffffu, mt, 2));
            float nm = fmaxf(m1, mt);
            float al = ex2(m1 - nm);
            m1 = nm;
            float rs = 0.f;
#pragma unroll
            for (int nt = 0; nt < 8; nt++) {
                s[nt][2] = ex2(s[nt][2] - nm);
                s[nt][3] = ex2(s[nt][3] - nm);
                rs += s[nt][2] + s[nt][3];
            }
            rs += __shfl_xor_sync(0xffffffffu, rs, 1);
            rs += __shfl_xor_sync(0xffffffffu, rs, 2);
            l1 = l1 * al + rs;
#pragma unroll
            for (int nt = 0; nt < 8; nt++) { o[nt][2] *= al; o[nt][3] *= al; }
        }

        // ---- O += P V (C-frag -> A-frag via quad shuffles)
#pragma unroll
        for (int ks = 0; ks < 8; ks++) {
            float c0A = __shfl_sync(0xffffffffu, s[ks][0], srcA);
            float c1A = __shfl_sync(0xffffffffu, s[ks][1], srcA);
            float c0B = __shfl_sync(0xffffffffu, s[ks][0], srcB);
            float c1B = __shfl_sync(0xffffffffu, s[ks][1], srcB);
            float c2A = __shfl_sync(0xffffffffu, s[ks][2], srcA);
            float c3A = __shfl_sync(0xffffffffu, s[ks][3], srcA);
            float c2B = __shfl_sync(0xffffffffu, s[ks][2], srcB);
            float c3B = __shfl_sync(0xffffffffu, s[ks][3], srcB);
            uint32_t a0 = f2tf(odd ? c1A : c0A);
            uint32_t a1 = f2tf(odd ? c3A : c2A);
            uint32_t a2 = f2tf(odd ? c1B : c0B);
            uint32_t a3 = f2tf(odd ? c3B : c2B);
            const int kc = ks * 8 + 2 * q4;
#pragma unroll
            for (int nt = 0; nt < 8; nt++) {
                int dd = nt * 8 + (lane >> 2);
                uint2 b = *(const uint2*)&Vb[dd * ST + kc];
                mma_tf32(o[nt][0], o[nt][1], o[nt][2], o[nt][3],
                         a0, a1, a2, a3, b.x, b.y);
            }
        }

        __syncthreads();
        if (t + 2 < NTILES) {
            int tn = t + 2;
            const float* kt = kg + (size_t)tn * KT * HD;
            int buf = tn & 1;
#pragma unroll
            for (int i = 0; i < 4; i++) {
                int id = tid + i * 256;
                int r = id >> 4, c = (id & 15) * 4;
                cp16(ks_u32 + (uint32_t)(buf * KT * ST + r * ST + c) * 4, kt + r * HD + c);
                cp16(vs_u32 + (uint32_t)(buf * KT * ST + r * ST + c) * 4,
                     vtg + (size_t)r * N_TOK + tn * KT + c);
            }
        }
        CP_COMMIT();
    }

    // ---- write unnormalized partials + (m, l)
    float* po = g_po + ((size_t)(sp * NH + h) * N_TOK) * HD;
    int row0 = qb * 128 + qrow;
#pragma unroll
    for (int nt = 0; nt < 8; nt++) {
        int dd = nt * 8 + 2 * q4;
        *(float2*)(po + (size_t)row0 * HD + dd) = make_float2(o[nt][0], o[nt][1]);
        *(float2*)(po + (size_t)(row0 + 8) * HD + dd) = make_float2(o[nt][2], o[nt][3]);
    }
    if (q4 == 0) {
        size_t mb = (size_t)(sp * NH + h) * N_TOK;
        g_pm[mb + row0] = m0;
        g_pl[mb + row0] = l0;
        g_pm[mb + row0 + 8] = m1;
        g_pl[mb + row0 + 8] = l1;
    }
}

// ---------------------------------------------------------------------------
// Split-K combine: O = (O0*w0 + O1*w1) / (l0*w0 + l1*w1), w_s = 2^(m_s - m*)
// Writes tf32-rounded g_att[n][h*HD+d]. Block: 16 rows x 64 cols.
// ---------------------------------------------------------------------------
__global__ void __launch_bounds__(256) attn_combine()
{
    const int h = blockIdx.y;
    const int tid = threadIdx.x;
    const int n = blockIdx.x * 16 + (tid >> 4);
    const int c = (tid & 15) * 4;

    size_t mb0 = (size_t)h * N_TOK + n;
    size_t mb1 = (size_t)(NH + h) * N_TOK + n;
    float m0 = g_pm[mb0], m1 = g_pm[mb1];
    float l0 = g_pl[mb0], l1 = g_pl[mb1];
    float ms = fmaxf(m0, m1);
    float w0 = ex2(m0 - ms), w1 = ex2(m1 - ms);
    float inv = 1.f / (l0 * w0 + l1 * w1);
    float a0 = w0 * inv, a1 = w1 * inv;

    float4 O0 = *(const float4*)(g_po + (mb0) * HD + c);
    float4 O1 = *(const float4*)(g_po + (mb1) * HD + c);
    float4 r = make_float4(
        __uint_as_float(f2tf(O0.x * a0 + O1.x * a1)),
        __uint_as_float(f2tf(O0.y * a0 + O1.y * a1)),
        __uint_as_float(f2tf(O0.z * a0 + O1.z * a1)),
        __uint_as_float(f2tf(O0.w * a0 + O1.w * a1)));
    *(float4*)(g_att + (size_t)n * DMODEL + h * HD + c) = r;
}

// ---------------------------------------------------------------------------
extern "C" void kernel_launch(void* const* d_in, const int* in_sizes, int n_in,
                              void* d_out, int out_size)
{
    (void)in_sizes; (void)n_in; (void)out_size;
    const float* hs     = (const float*)d_in[0];
    const float* cosp   = (const float*)d_in[1];
    const float* sinp   = (const float*)d_in[2];
    const float* qkv_w  = (const float*)d_in[3];
    const float* qkv_b  = (const float*)d_in[4];
    const float* proj_w = (const float*)d_in[5];
    const float* proj_b = (const float*)d_in[6];
    float* out = (float*)d_out;

    void *p_qkv = nullptr, *p_att = nullptr, *p_hs = nullptr, *p_w1 = nullptr, *p_w2 = nullptr;
    cudaGetSymbolAddress(&p_qkv, g_qkv);
    cudaGetSymbolAddress(&p_att, g_att);
    cudaGetSymbolAddress(&p_hs, g_hs);
    cudaGetSymbolAddress(&p_w1, g_w1);
    cudaGetSymbolAddress(&p_w2, g_w2);

    static bool attr_set = false;
    if (!attr_set) {
        cudaFuncSetAttribute(attn_mma, cudaFuncAttributeMaxDynamicSharedMemorySize, ATTN_SMEM);
        cudaFuncSetAttribute(gemm_tf32, cudaFuncAttributeMaxDynamicSharedMemorySize, GEMM_SMEM);
        attr_set = true;
    }

    // 0) pre-round hs / qkv_w / proj_w to tf32
    {
        int total4 = N_HS4 + N_W14 + N_W24;
        preround<<<(total4 + 255) / 256, 256>>>(
            (const float4*)hs, (const float4*)qkv_w, (const float4*)proj_w);
    }

    // 1) QKV = hs @ qkv_w + qkv_b        (4096 x 2304 x 768)
    gemm_tf32<<<dim3(3 * DMODEL / 128, N_TOK / 128), 256, GEMM_SMEM>>>(
        (const float*)p_hs, (const float*)p_w1, qkv_b, (float*)p_qkv,
        N_TOK, 3 * DMODEL, DMODEL);

    // 2) RoPE + scale(*log2e) + split q/k (d-permuted, tf32)
    rope_split<<<(N_TOK * NH * HD + 255) / 256, 256>>>(cosp, sinp);

    // 2b) V transpose to [h][d][perm(n)] (tf32)
    v_transpose<<<dim3(N_TOK / 64, NH), 256>>>();

    // 3) Flash attention, split-K over 2 key ranges
    attn_mma<<<dim3(N_TOK / 128, NH, NSPLIT), 256, ATTN_SMEM>>>();

    // 3b) combine partials
    attn_combine<<<dim3(N_TOK / 16, NH), 256>>>();

    // 4) out = att @ proj_w + proj_b     (4096 x 768 x 768)
    gemm_tf32<<<dim3(DMODEL / 128, N_TOK / 128), 256, GEMM_SMEM>>>(
        (const float*)p_att, (const float*)p_w2, proj_b, out,
        N_TOK, DMODEL, DMODEL);
}

// round 6
// speedup vs baseline: 1.7688x; 1.7688x over previous
#include <cuda_runtime.h>
#include <cuda_fp16.h>
#include <cstdint>

#define N_TOK 4096
#define NH 12
#define HD 64
#define DMODEL 768
#define QK_SCALE 0.125f
#define LOG2E 1.4426950408889634f
#define NSPLIT 2
#define KEYS_PER_SPLIT (N_TOK / NSPLIT)

// Scratch (device globals: allocation-free per harness rules)
__device__ float  g_qkv[(size_t)N_TOK * 3 * DMODEL];   // raw qkv (fp32)
__device__ __half g_hs[(size_t)N_TOK * DMODEL];        // fp16 hidden_states, word-permuted k
__device__ __half g_w1t[(size_t)3 * DMODEL * DMODEL];  // fp16 qkv_w^T [n][k], word-permuted k
__device__ __half g_w2t[(size_t)DMODEL * DMODEL];      // fp16 proj_w^T [n][k], word-permuted k
__device__ __half g_q[(size_t)NH * N_TOK * HD];        // [h][n][d-perm], *scale*log2e
__device__ __half g_k[(size_t)NH * N_TOK * HD];        // [h][n][d-perm]
__device__ __half g_vt[(size_t)NH * HD * N_TOK];       // [h][d][key-perm] V^T
__device__ __half g_att[(size_t)N_TOK * DMODEL];       // attn out [n][h*HD+d], word-permuted
// split-K partials
__device__ float g_po[(size_t)NSPLIT * NH * N_TOK * HD];
__device__ float g_pm[(size_t)NSPLIT * NH * N_TOK];
__device__ float g_pl[(size_t)NSPLIT * NH * N_TOK];

// ---------------------------------------------------------------------------
// helpers
// ---------------------------------------------------------------------------
__device__ __forceinline__ float ex2(float x) {
    float y;
    asm("ex2.approx.f32 %0, %1;" : "=f"(y) : "f"(x));
    return y;
}
__device__ __forceinline__ void mma_fp16(float& c0, float& c1, float& c2, float& c3,
                                         uint32_t a0, uint32_t a1, uint32_t a2, uint32_t a3,
                                         uint32_t b0, uint32_t b1) {
    asm volatile(
        "mma.sync.aligned.m16n8k16.row.col.f32.f16.f16.f32 "
        "{%0,%1,%2,%3}, {%4,%5,%6,%7}, {%8,%9}, {%0,%1,%2,%3};\n"
        : "+f"(c0), "+f"(c1), "+f"(c2), "+f"(c3)
        : "r"(a0), "r"(a1), "r"(a2), "r"(a3), "r"(b0), "r"(b1));
}
__device__ __forceinline__ void cp16(uint32_t dst, const void* src) {
    asm volatile("cp.async.cg.shared.global [%0], [%1], 16;" :: "r"(dst), "l"(src));
}
#define CP_COMMIT() asm volatile("cp.async.commit_group;")
#define CP_WAIT(n)  asm volatile("cp.async.wait_group %0;" :: "n"(n))

// pair-interleave permutation on 32-bit words within each 8-word (16-half) group
__device__ __forceinline__ int wperm(int w) {
    int r = w & 7;
    return (w & ~7) | ((r < 4) ? (2 * r) : (2 * (r - 4) + 1));
}
__device__ __forceinline__ uint32_t pack2(float lo, float hi) {
    __half2 h = __floats2half2_rn(lo, hi);
    return *reinterpret_cast<uint32_t*>(&h);
}

// ---------------------------------------------------------------------------
// hs -> fp16, word-permuted k
// ---------------------------------------------------------------------------
__global__ void __launch_bounds__(256) convert_hs(const float* __restrict__ hs)
{
    int i = blockIdx.x * 256 + threadIdx.x;        // word index
    if (i >= N_TOK * DMODEL / 2) return;
    int row = i / (DMODEL / 2);
    int w = i % (DMODEL / 2);
    float2 v = *(const float2*)(hs + (size_t)row * DMODEL + w * 2);
    ((__half2*)g_hs)[(size_t)row * (DMODEL / 2) + wperm(w)] = __floats2half2_rn(v.x, v.y);
}

// ---------------------------------------------------------------------------
// W[K][N] -> WT[n][k] fp16, word-permuted k. 64x64 tiles.
// ---------------------------------------------------------------------------
__global__ void __launch_bounds__(256) transpose_w(const float* __restrict__ W,
                                                   __half* __restrict__ WT,
                                                   int K, int N)
{
    __shared__ float sm[64][65];
    const int n0 = blockIdx.x * 64, k0 = blockIdx.y * 64;
    const int tid = threadIdx.x;
#pragma unroll
    for (int i = 0; i < 16; i++) {
        int id = tid + i * 256;
        int kl = id >> 6, nl = id & 63;
        sm[kl][nl] = W[(size_t)(k0 + kl) * N + n0 + nl];
    }
    __syncthreads();
#pragma unroll
    for (int i = 0; i < 8; i++) {
        int id = tid + i * 256;
        int nl = id >> 5, wl = id & 31;
        int kl = wl * 2;
        __half2 v = __floats2half2_rn(sm[kl][nl], sm[kl + 1][nl]);
        int Wg = (k0 >> 1) + wl;
        ((__half2*)WT)[(size_t)(n0 + nl) * (K >> 1) + wperm(Wg)] = v;
    }
}

// ---------------------------------------------------------------------------
// fp16 GEMM: C[M,Nc] = A[M,K] @ BT[Nc,K]^T + bias.
// A,BT fp16 word-permuted k. 128x128x64 tiles, 256 thr, 2 CTA/SM, cp.async 2-buf.
// ---------------------------------------------------------------------------
#define AW 40                     // word stride (== 8 mod 32 -> conflict-free)
#define ABUF (128 * AW)
#define GEMM_SMEM (4 * ABUF * 4)

__global__ void __launch_bounds__(256, 2) gemm_fp16(
    const __half* __restrict__ A, const __half* __restrict__ BT,
    const float* __restrict__ bias, float* __restrict__ C,
    int M, int Nc, int K)
{
    extern __shared__ uint32_t smg[];
    uint32_t* As = smg;                 // [2][128][AW]
    uint32_t* Bs = smg + 2 * ABUF;      // [2][128][AW]

    const int tid = threadIdx.x;
    const int lane = tid & 31;
    const int w = tid >> 5;
    const int wm = w >> 2, wn = w & 3;
    const int q4 = lane & 3;
    const int bx = blockIdx.x, by = blockIdx.y;

    const __half* Ag = A + (size_t)(by * 128) * K;
    const __half* Bg = BT + (size_t)(bx * 128) * K;

    const uint32_t as_u = (uint32_t)__cvta_generic_to_shared(As);
    const uint32_t bs_u = (uint32_t)__cvta_generic_to_shared(Bs);

    float acc[4][4][4];
#pragma unroll
    for (int mt = 0; mt < 4; mt++)
#pragma unroll
        for (int nt = 0; nt < 4; nt++)
#pragma unroll
            for (int c = 0; c < 4; c++) acc[mt][nt][c] = 0.f;

    const int NC = K / 64;

#pragma unroll
    for (int i = 0; i < 4; i++) {
        int id = tid + i * 256;
        int r = id >> 3, c8 = (id & 7) * 8;
        cp16(as_u + (uint32_t)(r * AW + (id & 7) * 4) * 4, Ag + (size_t)r * K + c8);
        cp16(bs_u + (uint32_t)(r * AW + (id & 7) * 4) * 4, Bg + (size_t)r * K + c8);
    }
    CP_COMMIT();

    for (int ch = 0; ch < NC; ch++) {
        if (ch + 1 < NC) {
            int k0 = (ch + 1) * 64;
            int buf = (ch + 1) & 1;
#pragma unroll
            for (int i = 0; i < 4; i++) {
                int id = tid + i * 256;
                int r = id >> 3, c8 = (id & 7) * 8;
                cp16(as_u + (uint32_t)(buf * ABUF + r * AW + (id & 7) * 4) * 4,
                     Ag + (size_t)r * K + k0 + c8);
                cp16(bs_u + (uint32_t)(buf * ABUF + r * AW + (id & 7) * 4) * 4,
                     Bg + (size_t)r * K + k0 + c8);
            }
        }
        CP_COMMIT();
        CP_WAIT(1);
        __syncthreads();

        const uint32_t* Ab = As + (ch & 1) * ABUF;
        const uint32_t* Bb = Bs + (ch & 1) * ABUF;

#pragma unroll
        for (int ks = 0; ks < 4; ks++) {
            const int wc = ks * 8 + 2 * q4;
            uint2 a[4][2];
#pragma unroll
            for (int mt = 0; mt < 4; mt++) {
                int r = wm * 64 + mt * 16 + (lane >> 2);
                a[mt][0] = *(const uint2*)&Ab[r * AW + wc];
                a[mt][1] = *(const uint2*)&Ab[(r + 8) * AW + wc];
            }
            uint2 b[4];
#pragma unroll
            for (int nt = 0; nt < 4; nt++) {
                int n = wn * 32 + nt * 8 + (lane >> 2);
                b[nt] = *(const uint2*)&Bb[n * AW + wc];
            }
#pragma unroll
            for (int mt = 0; mt < 4; mt++)
#pragma unroll
                for (int nt = 0; nt < 4; nt++)
                    mma_fp16(acc[mt][nt][0], acc[mt][nt][1], acc[mt][nt][2], acc[mt][nt][3],
                             a[mt][0].x, a[mt][1].x, a[mt][0].y, a[mt][1].y,
                             b[nt].x, b[nt].y);
        }
        __syncthreads();
    }

#pragma unroll
    for (int mt = 0; mt < 4; mt++) {
#pragma unroll
        for (int nt = 0; nt < 4; nt++) {
            int r = by * 128 + wm * 64 + mt * 16 + (lane >> 2);
            int cn = bx * 128 + wn * 32 + nt * 8 + 2 * q4;
            float b0 = bias[cn], b1 = bias[cn + 1];
            float2 v0 = make_float2(acc[mt][nt][0] + b0, acc[mt][nt][1] + b1);
            float2 v1 = make_float2(acc[mt][nt][2] + b0, acc[mt][nt][3] + b1);
            *(float2*)(C + (size_t)r * Nc + cn) = v0;
            *(float2*)(C + (size_t)(r + 8) * Nc + cn) = v1;
        }
    }
}

// ---------------------------------------------------------------------------
// RoPE + scale + split q/k -> fp16 [h][n][d-word-perm]; word-granular (d pairs)
// ---------------------------------------------------------------------------
__global__ void __launch_bounds__(256) rope_split(const float* __restrict__ cosp,
                                                  const float* __restrict__ sinp)
{
    int idx = blockIdx.x * 256 + threadIdx.x;
    if (idx >= N_TOK * NH * 32) return;
    int w = idx & 31;
    int h = (idx >> 5) % NH;
    int n = idx / (NH * 32);
    int d0 = 2 * w, d1 = 2 * w + 1;   // same half (both <32 or both >=32)

    float c0 = cosp[n * HD + d0], c1 = cosp[n * HD + d1];
    float s0 = sinp[n * HD + d0], s1 = sinp[n * HD + d1];
    const float* base = g_qkv + (size_t)n * (3 * DMODEL) + h * HD;
    int dp0 = (d0 < 32) ? d0 + 32 : d0 - 32;
    int dp1 = (d1 < 32) ? d1 + 32 : d1 - 32;
    float sgn = (d0 < 32) ? -1.f : 1.f;

    float q0 = (base[d0] * c0 + sgn * base[dp0] * s0) * (QK_SCALE * LOG2E);
    float q1 = (base[d1] * c1 + sgn * base[dp1] * s1) * (QK_SCALE * LOG2E);
    float k0 = base[DMODEL + d0] * c0 + sgn * base[DMODEL + dp0] * s0;
    float k1 = base[DMODEL + d1] * c1 + sgn * base[DMODEL + dp1] * s1;

    size_t o = ((size_t)h * N_TOK + n) * 32 + wperm(w);
    ((__half2*)g_q)[o] = __floats2half2_rn(q0, q1);
    ((__half2*)g_k)[o] = __floats2half2_rn(k0, k1);
}

// ---------------------------------------------------------------------------
// V transpose: g_qkv v-part [n][h*64+d] -> g_vt [h][d][key-word-perm] fp16
// ---------------------------------------------------------------------------
__global__ void __launch_bounds__(256) v_transpose()
{
    __shared__ float sm[64][65];
    const int h = blockIdx.y;
    const int nb = blockIdx.x;
    const int tid = threadIdx.x;

#pragma unroll
    for (int i = 0; i < 16; i++) {
        int idx = tid + i * 256;
        int nl = idx >> 6, d = idx & 63;
        sm[nl][d] = g_qkv[(size_t)(nb * 64 + nl) * (3 * DMODEL) + 2 * DMODEL + h * HD + d];
    }
    __syncthreads();
#pragma unroll
    for (int i = 0; i < 8; i++) {
        int idx = tid + i * 256;
        int dl = idx >> 5, wl = idx & 31;
        __half2 v = __floats2half2_rn(sm[2 * wl][dl], sm[2 * wl + 1][dl]);
        ((__half2*)g_vt)[((size_t)(h * HD + dl)) * (N_TOK / 2) + nb * 32 + wperm(wl)] = v;
    }
}

// ---------------------------------------------------------------------------
// Flash attention, split-K, fp16 m16n8k16, LDS.64 frags, cp.async 2-buf 64-key tiles
// ---------------------------------------------------------------------------
#define KT 64
#define NTILES (KEYS_PER_SPLIT / KT)   // 32
#define SW 40                          // word stride
#define QBUF (128 * SW)
#define KBUF (KT * SW)
#define ATTN_SMEM ((QBUF + 2 * KBUF + 2 * KBUF) * 4)

__global__ void __launch_bounds__(256, 2) attn_mma()
{
    extern __shared__ uint32_t sm[];
    uint32_t* Qs = sm;                 // [128][SW]
    uint32_t* Ks = Qs + QBUF;          // [2][64 keys][SW]  (32 d-words used)
    uint32_t* Vs = Ks + 2 * KBUF;      // [2][64 d][SW]     (32 key-words used)

    const int h = blockIdx.y;
    const int qb = blockIdx.x;
    const int sp = blockIdx.z;
    const int tid = threadIdx.x;
    const int lane = tid & 31;
    const int w = tid >> 5;
    const int q4 = lane & 3;

    const __half* qg = g_q + ((size_t)h * N_TOK + (size_t)qb * 128) * HD;
    const __half* kg = g_k + ((size_t)h * N_TOK + (size_t)sp * KEYS_PER_SPLIT) * HD;
    const __half* vtg = g_vt + (size_t)h * HD * N_TOK + (size_t)sp * KEYS_PER_SPLIT;

    const uint32_t ks_u32 = (uint32_t)__cvta_generic_to_shared(Ks);
    const uint32_t vs_u32 = (uint32_t)__cvta_generic_to_shared(Vs);

    // load Q tile (fp16, already word-permuted): 128 rows x 32 words
#pragma unroll
    for (int i = 0; i < 4; i++) {
        int id = tid + i * 256;
        int r = id >> 3, wc = (id & 7) * 4;
        *(uint4*)&Qs[r * SW + wc] = *(const uint4*)(qg + (size_t)r * HD + wc * 2);
    }

    // prefetch key tiles 0 and 1
#pragma unroll
    for (int t = 0; t < 2; t++) {
#pragma unroll
        for (int i = 0; i < 2; i++) {
            int id = tid + i * 256;
            int r = id >> 3, c8 = (id & 7) * 8;
            cp16(ks_u32 + (uint32_t)(t * KBUF + r * SW + (id & 7) * 4) * 4,
                 kg + ((size_t)t * KT + r) * HD + c8);
            cp16(vs_u32 + (uint32_t)(t * KBUF + r * SW + (id & 7) * 4) * 4,
                 vtg + (size_t)r * N_TOK + t * KT + c8);
        }
        CP_COMMIT();
    }

    float o[8][4];
#pragma unroll
    for (int nt = 0; nt < 8; nt++)
#pragma unroll
        for (int c = 0; c < 4; c++) o[nt][c] = 0.f;
    float m0 = -1e30f, m1 = -1e30f, l0 = 0.f, l1 = 0.f;

    const int qrow = w * 16 + (lane >> 2);

    for (int t = 0; t < NTILES; t++) {
        CP_WAIT(1);
        __syncthreads();
        const uint32_t* Kb = Ks + (t & 1) * KBUF;
        const uint32_t* Vb = Vs + (t & 1) * KBUF;

        // ---- S = Q K^T : 4 k16-steps over d, 8 n-tiles over 64 keys
        float s[8][4];
#pragma unroll
        for (int nt = 0; nt < 8; nt++)
#pragma unroll
            for (int c = 0; c < 4; c++) s[nt][c] = 0.f;

#pragma unroll
        for (int ks = 0; ks < 4; ks++) {
            const int wc = ks * 8 + 2 * q4;
            uint2 aA = *(const uint2*)&Qs[qrow * SW + wc];
            uint2 aB = *(const uint2*)&Qs[(qrow + 8) * SW + wc];
#pragma unroll
            for (int nt = 0; nt < 8; nt++) {
                int nn = nt * 8 + (lane >> 2);
                uint2 b = *(const uint2*)&Kb[nn * SW + wc];
                mma_fp16(s[nt][0], s[nt][1], s[nt][2], s[nt][3],
                         aA.x, aB.x, aA.y, aB.y, b.x, b.y);
            }
        }

        // ---- online softmax (log2 domain; rows qrow, qrow+8)
        {
            float mt = -1e30f;
#pragma unroll
            for (int nt = 0; nt < 8; nt++)
                mt = fmaxf(mt, fmaxf(s[nt][0], s[nt][1]));
            mt = fmaxf(mt, __shfl_xor_sync(0xffffffffu, mt, 1));
            mt = fmaxf(mt, __shfl_xor_sync(0xffffffffu, mt, 2));
            float nm = fmaxf(m0, mt);
            float al = ex2(m0 - nm);
            m0 = nm;
            float rs = 0.f;
#pragma unroll
            for (int nt = 0; nt < 8; nt++) {
                s[nt][0] = ex2(s[nt][0] - nm);
                s[nt][1] = ex2(s[nt][1] - nm);
                rs += s[nt][0] + s[nt][1];
            }
            rs += __shfl_xor_sync(0xffffffffu, rs, 1);
            rs += __shfl_xor_sync(0xffffffffu, rs, 2);
            l0 = l0 * al + rs;
#pragma unroll
            for (int nt = 0; nt < 8; nt++) { o[nt][0] *= al; o[nt][1] *= al; }
        }
        {
            float mt = -1e30f;
#pragma unroll
            for (int nt = 0; nt < 8; nt++)
                mt = fmaxf(mt, fmaxf(s[nt][2], s[nt][3]));
            mt = fmaxf(mt, __shfl_xor_sync(0xffffffffu, mt, 1));
            mt = fmaxf(mt, __shfl_xor_sync(0xffffffffu, mt, 2));
            float nm = fmaxf(m1, mt);
            float al = ex2(m1 - nm);
            m1 = nm;
            float rs = 0.f;
#pragma unroll
            for (int nt = 0; nt < 8; nt++) {
                s[nt][2] = ex2(s[nt][2] - nm);
                s[nt][3] = ex2(s[nt][3] - nm);
                rs += s[nt][2] + s[nt][3];
            }
            rs += __shfl_xor_sync(0xffffffffu, rs, 1);
            rs += __shfl_xor_sync(0xffffffffu, rs, 2);
            l1 = l1 * al + rs;
#pragma unroll
            for (int nt = 0; nt < 8; nt++) { o[nt][2] *= al; o[nt][3] *= al; }
        }

        // ---- O += P V : fp16 C-frag == A-frag lane layout; just pack (no shuffles)
#pragma unroll
        for (int kg = 0; kg < 4; kg++) {     // 16-key groups
            uint32_t a0 = pack2(s[2 * kg][0], s[2 * kg][1]);
            uint32_t a1 = pack2(s[2 * kg][2], s[2 * kg][3]);
            uint32_t a2 = pack2(s[2 * kg + 1][0], s[2 * kg + 1][1]);
            uint32_t a3 = pack2(s[2 * kg + 1][2], s[2 * kg + 1][3]);
            const int wc = kg * 8 + 2 * q4;
#pragma unroll
            for (int nt = 0; nt < 8; nt++) {
                int dd = nt * 8 + (lane >> 2);
                uint2 b = *(const uint2*)&Vb[dd * SW + wc];
                mma_fp16(o[nt][0], o[nt][1], o[nt][2], o[nt][3],
                         a0, a1, a2, a3, b.x, b.y);
            }
        }

        __syncthreads();
        if (t + 2 < NTILES) {
            int tn = t + 2;
            int buf = tn & 1;
#pragma unroll
            for (int i = 0; i < 2; i++) {
                int id = tid + i * 256;
                int r = id >> 3, c8 = (id & 7) * 8;
                cp16(ks_u32 + (uint32_t)(buf * KBUF + r * SW + (id & 7) * 4) * 4,
                     kg + ((size_t)tn * KT + r) * HD + c8);
                cp16(vs_u32 + (uint32_t)(buf * KBUF + r * SW + (id & 7) * 4) * 4,
                     vtg + (size_t)r * N_TOK + tn * KT + c8);
            }
        }
        CP_COMMIT();
    }

    // ---- write unnormalized partials + (m, l)
    float* po = g_po + ((size_t)(sp * NH + h) * N_TOK) * HD;
    int row0 = qb * 128 + qrow;
#pragma unroll
    for (int nt = 0; nt < 8; nt++) {
        int dd = nt * 8 + 2 * q4;
        *(float2*)(po + (size_t)row0 * HD + dd) = make_float2(o[nt][0], o[nt][1]);
        *(float2*)(po + (size_t)(row0 + 8) * HD + dd) = make_float2(o[nt][2], o[nt][3]);
    }
    if (q4 == 0) {
        size_t mb = (size_t)(sp * NH + h) * N_TOK;
        g_pm[mb + row0] = m0;
        g_pl[mb + row0] = l0;
        g_pm[mb + row0 + 8] = m1;
        g_pl[mb + row0 + 8] = l1;
    }
}

// ---------------------------------------------------------------------------
// Split-K combine -> fp16 word-permuted g_att[n][h*HD+d]
// ---------------------------------------------------------------------------
__global__ void __launch_bounds__(256) attn_combine()
{
    const int h = blockIdx.y;
    const int tid = threadIdx.x;
    const int n = blockIdx.x * 16 + (tid >> 4);
    const int c = (tid & 15) * 4;

    size_t mb0 = (size_t)h * N_TOK + n;
    size_t mb1 = (size_t)(NH + h) * N_TOK + n;
    float m0 = g_pm[mb0], m1 = g_pm[mb1];
    float l0 = g_pl[mb0], l1 = g_pl[mb1];
    float ms = fmaxf(m0, m1);
    float w0 = ex2(m0 - ms), w1 = ex2(m1 - ms);
    float inv = 1.f / (l0 * w0 + l1 * w1);
    float a0 = w0 * inv, a1 = w1 * inv;

    float4 O0 = *(const float4*)(g_po + mb0 * HD + c);
    float4 O1 = *(const float4*)(g_po + mb1 * HD + c);
    int W = (h * HD + c) >> 1;
    ((__half2*)g_att)[(size_t)n * (DMODEL / 2) + wperm(W)] =
        __floats2half2_rn(O0.x * a0 + O1.x * a1, O0.y * a0 + O1.y * a1);
    ((__half2*)g_att)[(size_t)n * (DMODEL / 2) + wperm(W + 1)] =
        __floats2half2_rn(O0.z * a0 + O1.z * a1, O0.w * a0 + O1.w * a1);
}

// ---------------------------------------------------------------------------
extern "C" void kernel_launch(void* const* d_in, const int* in_sizes, int n_in,
                              void* d_out, int out_size)
{
    (void)in_sizes; (void)n_in; (void)out_size;
    const float* hs     = (const float*)d_in[0];
    const float* cosp   = (const float*)d_in[1];
    const float* sinp   = (const float*)d_in[2];
    const float* qkv_w  = (const float*)d_in[3];
    const float* qkv_b  = (const float*)d_in[4];
    const float* proj_w = (const float*)d_in[5];
    const float* proj_b = (const float*)d_in[6];
    float* out = (float*)d_out;

    void *p_qkv = nullptr, *p_att = nullptr, *p_hs = nullptr, *p_w1t = nullptr, *p_w2t = nullptr;
    cudaGetSymbolAddress(&p_qkv, g_qkv);
    cudaGetSymbolAddress(&p_att, g_att);
    cudaGetSymbolAddress(&p_hs, g_hs);
    cudaGetSymbolAddress(&p_w1t, g_w1t);
    cudaGetSymbolAddress(&p_w2t, g_w2t);

    static bool attr_set = false;
    if (!attr_set) {
        cudaFuncSetAttribute(attn_mma, cudaFuncAttributeMaxDynamicSharedMemorySize, ATTN_SMEM);
        cudaFuncSetAttribute(gemm_fp16, cudaFuncAttributeMaxDynamicSharedMemorySize, GEMM_SMEM);
        attr_set = true;
    }

    // 0) convert inputs to fp16 (word-permuted k); transpose weights
    convert_hs<<<(N_TOK * DMODEL / 2 + 255) / 256, 256>>>(hs);
    transpose_w<<<dim3(3 * DMODEL / 64, DMODEL / 64), 256>>>(qkv_w, (__half*)p_w1t, DMODEL, 3 * DMODEL);
    transpose_w<<<dim3(DMODEL / 64, DMODEL / 64), 256>>>(proj_w, (__half*)p_w2t, DMODEL, DMODEL);

    // 1) QKV = hs @ qkv_w + qkv_b        (4096 x 2304 x 768)
    gemm_fp16<<<dim3(3 * DMODEL / 128, N_TOK / 128), 256, GEMM_SMEM>>>(
        (const __half*)p_hs, (const __half*)p_w1t, qkv_b, (float*)p_qkv,
        N_TOK, 3 * DMODEL, DMODEL);

    // 2) RoPE + scale(*log2e) + split q/k (fp16, word-permuted d)
    rope_split<<<(N_TOK * NH * 32 + 255) / 256, 256>>>(cosp, sinp);

    // 2b) V transpose to [h][d][key-perm] fp16
    v_transpose<<<dim3(N_TOK / 64, NH), 256>>>();

    // 3) Flash attention, split-K over 2 key ranges (fp16 mma)
    attn_mma<<<dim3(N_TOK / 128, NH, NSPLIT), 256, ATTN_SMEM>>>();

    // 3b) combine partials -> fp16 g_att
    attn_combine<<<dim3(N_TOK / 16, NH), 256>>>();

    // 4) out = att @ proj_w + proj_b     (4096 x 768 x 768)
    gemm_fp16<<<dim3(DMODEL / 128, N_TOK / 128), 256, GEMM_SMEM>>>(
        (const __half*)p_att, (const __half*)p_w2t, proj_b, out,
        N_TOK, DMODEL, DMODEL);
}